// round 4
// baseline (speedup 1.0000x reference)
#include <cuda_runtime.h>
#include <cstdint>

// MPS memory encoder:
//   x:     [B=2048, N=128, F=64]      f32
//   cores: [N=128, D=32, F=64, D=32]  f32
//   start: [1, 32], end: [32, 1], fc_w: [256,1], fc_b: [256]
//   out:   [B, 256] = (chain(res0=start; res <- res @ (x_i . core_i)) @ end) @ fc_w^T + fc_b
//
// Strategy this round: packed-fp32 (fma.rn.f32x2) CUDA-core kernel.
//   - CTA handles NB=8 batches, 256 threads, grid=256 -> 2 CTAs/SM.
//   - thread = (2 batches) x (4 r) x (4 d); d split 8 ways across threads,
//     per-site cross-thread reduction through padded smem.
//   - core streamed with LDG.128 (L2-resident: 32 MB total), warp-coalesced
//     into single 128B lines with batch-lane broadcast.

#define BATCH   2048
#define NSITES  128
#define FEAT    64
#define DBOND   32
#define OUTD    256
#define NB      8
#define THREADS 256

typedef unsigned long long u64;

__device__ __forceinline__ u64 pack2(float a, float b) {
    u64 r;
    asm("mov.b64 %0, {%1, %2};" : "=l"(r)
        : "r"(__float_as_uint(a)), "r"(__float_as_uint(b)));
    return r;
}

__device__ __forceinline__ u64 fma2(u64 a, u64 b, u64 c) {
    u64 d;
    asm("fma.rn.f32x2 %0, %1, %2, %3;" : "=l"(d) : "l"(a), "l"(b), "l"(c));
    return d;
}

__global__ __launch_bounds__(THREADS, 2)
void mps_encoder_kernel(const float* __restrict__ x,
                        const float* __restrict__ cores,
                        const float* __restrict__ start,
                        const float* __restrict__ endv,
                        const float* __restrict__ fc_w,
                        const float* __restrict__ fc_b,
                        float* __restrict__ out)
{
    // padded smem to keep LDS/STS conflict degree <= 2
    __shared__ float x_s[NB][68];       // x[b][f] for current site
    __shared__ float res_s[NB][33];     // running res vector per batch
    __shared__ float part[8][NB][36];   // per-dq partial res_new
    __shared__ float val_s[NB];

    const int tid = threadIdx.x;
    const int bp  = tid & 3;            // batch pair 0..3
    const int rq  = (tid >> 2) & 7;     // r quad 0..7  -> r0 = 4*rq
    const int dq  = tid >> 5;           // d quad 0..7  -> d0 = 4*dq
    const int b0  = 2 * bp;
    const int b1  = 2 * bp + 1;
    const int r0  = 4 * rq;
    const int d0  = 4 * dq;
    const int bbase = blockIdx.x * NB;

    // init running state: res = start (broadcast over batches)
    {
        int b = tid >> 5, d = tid & 31;     // 8*32 == 256 threads exactly
        res_s[b][d] = start[d];
    }

    // core viewed as ulonglong2 (= float4): element (site,d,f,r0..r0+3)
    //   float-index = ((site*32 + d)*64 + f)*32 + r0 ; /4 -> ull2 units
    const ulonglong2* cbase =
        reinterpret_cast<const ulonglong2*>(cores) + rq + (size_t)d0 * 512;
    const float4* x4 = reinterpret_cast<const float4*>(x);

    for (int site = 0; site < NSITES; ++site) {
        __syncthreads();   // (A) res_s from previous reduction visible; buffers free

        // stage x[b][site][:] -> x_s  (128 float4 loads by threads 0..127)
        if (tid < NB * 16) {
            int br = tid >> 4, q = tid & 15;
            float4 xv = x4[((size_t)(bbase + br) * NSITES + site) * 16 + q];
            *reinterpret_cast<float4*>(&x_s[br][q * 4]) = xv;
        }

        // pre-pack (res_d, res_d) register pairs for this thread's 4 d's
        u64 rp0[4], rp1[4];
        #pragma unroll
        for (int i = 0; i < 4; ++i) {
            float v0 = res_s[b0][d0 + i];
            float v1 = res_s[b1][d0 + i];
            rp0[i] = pack2(v0, v0);
            rp1[i] = pack2(v1, v1);
        }

        __syncthreads();   // (B) x_s ready; res reads complete before reduce rewrites

        const ulonglong2* cp = cbase + (size_t)site * 16384;

        u64 a00 = 0, a01 = 0, a10 = 0, a11 = 0;   // acc: (b0,r01)(b0,r23)(b1,r01)(b1,r23)

        #pragma unroll 2
        for (int f = 0; f < FEAT; ++f) {
            // 4 x LDG.128: core[d0..d0+3][f][r0..r0+3]; one 128B line per warp
            ulonglong2 c[4];
            #pragma unroll
            for (int i = 0; i < 4; ++i) c[i] = cp[i * 512];
            cp += 8;   // next f

            // s = sum_{d in mine} res_d * core[d][f][r]   (reset each f)
            u64 s00 = 0, s01 = 0, s10 = 0, s11 = 0;
            #pragma unroll
            for (int i = 0; i < 4; ++i) {
                s00 = fma2(rp0[i], c[i].x, s00);
                s01 = fma2(rp0[i], c[i].y, s01);
                s10 = fma2(rp1[i], c[i].x, s10);
                s11 = fma2(rp1[i], c[i].y, s11);
            }

            // acc += x_f * s
            float xf0 = x_s[b0][f];
            float xf1 = x_s[b1][f];
            u64 x20 = pack2(xf0, xf0);
            u64 x21 = pack2(xf1, xf1);
            a00 = fma2(x20, s00, a00);
            a01 = fma2(x20, s01, a01);
            a10 = fma2(x21, s10, a10);
            a11 = fma2(x21, s11, a11);
        }

        // write d-partials (u64 = two packed f32, lane order matches r0,r0+1)
        *reinterpret_cast<u64*>(&part[dq][b0][r0])     = a00;
        *reinterpret_cast<u64*>(&part[dq][b0][r0 + 2]) = a01;
        *reinterpret_cast<u64*>(&part[dq][b1][r0])     = a10;
        *reinterpret_cast<u64*>(&part[dq][b1][r0 + 2]) = a11;

        __syncthreads();   // (C) partials visible

        // reduce 8 d-quads -> new res (256 slots, one per thread)
        {
            int b = tid >> 5, r = tid & 31;
            float v = 0.0f;
            #pragma unroll
            for (int k = 0; k < 8; ++k) v += part[k][b][r];
            res_s[b][r] = v;
        }
    }

    __syncthreads();

    // val[b] = res[b] . end
    if (tid < NB) {
        float v = 0.0f;
        #pragma unroll
        for (int r = 0; r < DBOND; ++r) v += res_s[tid][r] * endv[r];
        val_s[tid] = v;
    }
    __syncthreads();

    // out[b][o] = val[b] * fc_w[o] + fc_b[o]   (o = tid, coalesced)
    {
        const float w  = fc_w[tid];
        const float bb = fc_b[tid];
        #pragma unroll
        for (int j = 0; j < NB; ++j) {
            out[(size_t)(bbase + j) * OUTD + tid] = val_s[j] * w + bb;
        }
    }
}

extern "C" void kernel_launch(void* const* d_in, const int* in_sizes, int n_in,
                              void* d_out, int out_size)
{
    (void)in_sizes; (void)n_in; (void)out_size;
    const float* x_p     = (const float*)d_in[0];
    const float* cores_p = (const float*)d_in[1];
    const float* start_p = (const float*)d_in[2];
    const float* end_p   = (const float*)d_in[3];
    const float* fcw_p   = (const float*)d_in[4];
    const float* fcb_p   = (const float*)d_in[5];
    float* out_p = (float*)d_out;

    mps_encoder_kernel<<<BATCH / NB, THREADS>>>(
        x_p, cores_p, start_p, end_p, fcw_p, fcb_p, out_p);
}

// round 6
// speedup vs baseline: 1.8406x; 1.8406x over previous
#include <cuda_runtime.h>
#include <cstdint>

// MPS memory encoder, Round 5: cp.async-staged, register-batched fma2 kernel.
//   x:     [B=2048, N=128, F=64]      f32
//   cores: [N=128, D=32, F=64, D=32]  f32  (site slice = 256KB, streamed via cp.async)
//   out[B,256] = (chain(res0=start; res <- res @ (x_i . core_i)) @ end) @ fc_w^T + fc_b
//
// Geometry: grid=128 CTAs x 256 threads, NB=16 batches/CTA.
//   thread = 4 batches x 4 r x 4 d  (bpl = tid&3, rq = (tid>>2)&7, dq = tid>>5)
//   warp   = fixed dq; lanes = 4 bpl x 8 rq -> each LDS.128 touches 128B distinct.
// Pipeline: triple-buffered 32KB chunks (8 f-slices of core), cp.async.cg,
//   one commit_group per chunk, wait_group 1 + one __syncthreads per chunk.

#define NSITES   128
#define FEAT     64
#define DB       32
#define OUTD     256
#define NB       16
#define THREADS  256
#define CH       8                       // f-slices per chunk
#define NCHUNK   (NSITES * FEAT / CH)    // 1024
#define CHUNK_BYTES   (DB * CH * DB * 4) // 32768
#define SITE_FLOATS   (DB * FEAT * DB)   // 131072

// smem byte offsets
#define BUF_OFF   0                      // [3][8192] floats
#define X_OFF     98304                  // [2][16][65] u64  (x duplicated pairs)
#define RES_OFF   114944                 // [16][33] floats
#define PART_OFF  117056                 // [8][16][36] floats
#define VAL_OFF   135488                 // [16] floats
#define SMEM_TOTAL 135616

typedef unsigned long long u64;

__device__ __forceinline__ u64 pack2(float a, float b) {
    u64 r;
    asm("mov.b64 %0, {%1, %2};" : "=l"(r)
        : "r"(__float_as_uint(a)), "r"(__float_as_uint(b)));
    return r;
}

__device__ __forceinline__ u64 fma2(u64 a, u64 b, u64 c) {
    u64 d;
    asm("fma.rn.f32x2 %0, %1, %2, %3;" : "=l"(d) : "l"(a), "l"(b), "l"(c));
    return d;
}

__device__ __forceinline__ void cp16(uint32_t dst, const float* src) {
    asm volatile("cp.async.cg.shared.global [%0], [%1], 16;\n"
                 :: "r"(dst), "l"(src));
}

__device__ __forceinline__ void issue_chunk(int g, int tid, uint32_t smem_base,
                                            const float* __restrict__ cores) {
    if (g < NCHUNK) {
        // gmem: float idx = site*131072 + d*2048 + c*256 + w*4  (site=g>>3, c=g&7)
        const float* base = cores + (size_t)(g >> 3) * SITE_FLOATS + (g & 7) * 256;
        uint32_t dst = smem_base + (uint32_t)((g % 3) * CHUNK_BYTES) + tid * 16;
        #pragma unroll
        for (int k = 0; k < 8; ++k) {
            int u = tid + k * 256;            // 16B unit id, 2048 per chunk
            int d = u >> 6, w = u & 63;
            cp16(dst + k * 4096, base + d * 2048 + w * 4);
        }
    }
    asm volatile("cp.async.commit_group;\n");   // always commit (uniform counting)
}

__global__ __launch_bounds__(THREADS, 1)
void mps_encoder_kernel(const float* __restrict__ x,
                        const float* __restrict__ cores,
                        const float* __restrict__ start,
                        const float* __restrict__ endv,
                        const float* __restrict__ fc_w,
                        const float* __restrict__ fc_b,
                        float* __restrict__ out)
{
    extern __shared__ char smem[];
    float* buff  = (float*)(smem + BUF_OFF);
    u64*   x2    = (u64*)  (smem + X_OFF);     // [2][16][65]
    float* res_s = (float*)(smem + RES_OFF);   // [16][33]
    float* part  = (float*)(smem + PART_OFF);  // [8][16][36]
    float* val_s = (float*)(smem + VAL_OFF);

    const uint32_t smem_base = (uint32_t)__cvta_generic_to_shared(smem);

    const int tid = threadIdx.x;
    const int bpl = tid & 3;            // batch group: batches B0..B0+3
    const int rq  = (tid >> 2) & 7;     // r quad
    const int dq  = tid >> 5;           // warp id = d quad
    const int r0  = 4 * rq;
    const int d0  = 4 * dq;
    const int B0  = 4 * bpl;
    const int bbase = blockIdx.x * NB;

    // init res = start (512 slots, 2 per thread)
    #pragma unroll
    for (int s2 = tid; s2 < NB * DB; s2 += THREADS)
        res_s[(s2 >> 5) * 33 + (s2 & 31)] = start[s2 & 31];

    const float4* x4 = reinterpret_cast<const float4*>(x);

    // stage x for site 0 into x-buffer 0 (duplicated pairs)
    {
        int br = tid >> 4, q = tid & 15;
        float4 xv = x4[((size_t)(bbase + br) * NSITES + 0) * 16 + q];
        u64* dstx = &x2[(size_t)br * 65 + 4 * q];
        dstx[0] = pack2(xv.x, xv.x); dstx[1] = pack2(xv.y, xv.y);
        dstx[2] = pack2(xv.z, xv.z); dstx[3] = pack2(xv.w, xv.w);
    }

    // prologue: prefetch chunks 0 and 1
    issue_chunk(0, tid, smem_base, cores);
    issue_chunk(1, tid, smem_base, cores);

    u64 rp[4][4];     // rp[bb][i] = (res[B0+bb][d0+i], dup)
    const u64 zero = 0;

    for (int site = 0; site < NSITES; ++site) {
        u64 acc[4][2];
        #pragma unroll
        for (int bb = 0; bb < 4; ++bb) { acc[bb][0] = 0; acc[bb][1] = 0; }

        const u64* xrow = x2 + (size_t)((site & 1) * NB) * 65;

        for (int c = 0; c < CH; ++c) {
            const int g = site * CH + c;

            asm volatile("cp.async.wait_group 1;\n" ::: "memory");
            __syncthreads();                 // chunk g visible; prev buffers free
            issue_chunk(g + 2, tid, smem_base, cores);

            if (c == 0) {
                // stage x for next site (other x-buffer; read only next site)
                if (site + 1 < NSITES) {
                    int br = tid >> 4, q = tid & 15;
                    float4 xv = x4[((size_t)(bbase + br) * NSITES + site + 1) * 16 + q];
                    u64* dstx = &x2[(size_t)(((site + 1) & 1) * NB + br) * 65 + 4 * q];
                    dstx[0] = pack2(xv.x, xv.x); dstx[1] = pack2(xv.y, xv.y);
                    dstx[2] = pack2(xv.z, xv.z); dstx[3] = pack2(xv.w, xv.w);
                }
                // pack res pairs for this site (reads res_s; covered by sync above)
                #pragma unroll
                for (int bb = 0; bb < 4; ++bb)
                    #pragma unroll
                    for (int i = 0; i < 4; ++i) {
                        float v = res_s[(B0 + bb) * 33 + d0 + i];
                        rp[bb][i] = pack2(v, v);
                    }
            }

            // compute 8 f-slices from staged chunk
            const float* cb = buff + (size_t)(g % 3) * (CHUNK_BYTES / 4) + d0 * 256 + r0;
            #pragma unroll 2
            for (int fl = 0; fl < CH; ++fl) {
                ulonglong2 c0 = *(const ulonglong2*)(cb       + fl * 32);
                ulonglong2 c1 = *(const ulonglong2*)(cb + 256 + fl * 32);
                ulonglong2 c2 = *(const ulonglong2*)(cb + 512 + fl * 32);
                ulonglong2 c3 = *(const ulonglong2*)(cb + 768 + fl * 32);
                const int fg = c * CH + fl;
                #pragma unroll
                for (int bb = 0; bb < 4; ++bb) {
                    u64 s0 = fma2(rp[bb][0], c0.x, zero);
                    u64 s1 = fma2(rp[bb][0], c0.y, zero);
                    s0 = fma2(rp[bb][1], c1.x, s0);
                    s1 = fma2(rp[bb][1], c1.y, s1);
                    s0 = fma2(rp[bb][2], c2.x, s0);
                    s1 = fma2(rp[bb][2], c2.y, s1);
                    s0 = fma2(rp[bb][3], c3.x, s0);
                    s1 = fma2(rp[bb][3], c3.y, s1);
                    u64 xv = xrow[(size_t)(B0 + bb) * 65 + fg];   // pre-duplicated (x,x)
                    acc[bb][0] = fma2(xv, s0, acc[bb][0]);
                    acc[bb][1] = fma2(xv, s1, acc[bb][1]);
                }
            }
        }

        // write d-quad partials
        #pragma unroll
        for (int bb = 0; bb < 4; ++bb) {
            float* pb = part + (size_t)(dq * NB + B0 + bb) * 36;
            *(u64*)(pb + r0)     = acc[bb][0];
            *(u64*)(pb + r0 + 2) = acc[bb][1];
        }
        __syncthreads();                    // partials visible

        // reduce 8 d-quads -> new res (512 slots, 2 per thread)
        #pragma unroll
        for (int s2 = tid; s2 < NB * DB; s2 += THREADS) {
            int b = s2 >> 5, r = s2 & 31;
            float v = 0.0f;
            #pragma unroll
            for (int k = 0; k < 8; ++k) v += part[(size_t)(k * NB + b) * 36 + r];
            res_s[b * 33 + r] = v;
        }
        // next site's first chunk-sync orders res_s writes before rp packing
    }

    __syncthreads();

    // val[b] = res[b] . end
    if (tid < NB) {
        float v = 0.0f;
        #pragma unroll
        for (int r = 0; r < DB; ++r) v += res_s[tid * 33 + r] * endv[r];
        val_s[tid] = v;
    }
    __syncthreads();

    // out[b][o] = val[b] * fc_w[o] + fc_b[o]
    {
        const float w  = fc_w[tid];
        const float bi = fc_b[tid];
        #pragma unroll
        for (int j = 0; j < NB; ++j)
            out[(size_t)(bbase + j) * OUTD + tid] = val_s[j] * w + bi;
    }
}

extern "C" void kernel_launch(void* const* d_in, const int* in_sizes, int n_in,
                              void* d_out, int out_size)
{
    (void)in_sizes; (void)n_in; (void)out_size;
    const float* x_p     = (const float*)d_in[0];
    const float* cores_p = (const float*)d_in[1];
    const float* start_p = (const float*)d_in[2];
    const float* end_p   = (const float*)d_in[3];
    const float* fcw_p   = (const float*)d_in[4];
    const float* fcb_p   = (const float*)d_in[5];
    float* out_p = (float*)d_out;

    cudaFuncSetAttribute(mps_encoder_kernel,
                         cudaFuncAttributeMaxDynamicSharedMemorySize, SMEM_TOTAL);

    mps_encoder_kernel<<<2048 / NB, THREADS, SMEM_TOTAL>>>(
        x_p, cores_p, start_p, end_p, fcw_p, fcb_p, out_p);
}

// round 7
// speedup vs baseline: 2.0358x; 1.1061x over previous
#include <cuda_runtime.h>
#include <cstdint>

// MPS memory encoder, Round 6: f-split 512-thread fma2 kernel.
//   x:     [B=2048, N=128, F=64]      f32
//   cores: [N=128, D=32, F=64, D=32]  f32  (site slice = 256KB, streamed via cp.async)
//   out[B,256] = (chain(res0=start; res <- res @ (x_i . core_i)) @ end) @ fc_w^T + fc_b
//
// Geometry: grid=128 CTAs x 512 threads, NB=16 batches/CTA.
//   fhalf = tid>>8 selects f-slices {0..3} or {4..7} of each staged chunk.
//   Within half: thread = 4 batches x 4 r x 4 d  (bpl=tid&3, rq=(tid>>2)&7, dq=(tid>>5)&7)
//   -> 16 warps/SM (4 per SMSP) for latency hiding; LDS keeps 4-way batch broadcast.
// Pipeline: triple-buffered 32KB chunks (8 f-slices), cp.async.cg, wait_group 1.

#define NSITES   128
#define FEAT     64
#define DB       32
#define OUTD     256
#define NB       16
#define THREADS  512
#define CH       8                       // f-slices per chunk
#define NCHUNK   (NSITES * FEAT / CH)    // 1024
#define CHUNK_BYTES   (DB * CH * DB * 4) // 32768
#define SITE_FLOATS   (DB * FEAT * DB)   // 131072

// smem byte offsets
#define BUF_OFF   0                      // [3][8192] floats
#define X_OFF     98304                  // [2][16][65] u64 (x duplicated pairs)
#define RES_OFF   114944                 // [16][33] floats
#define PART_OFF  117056                 // [16][16][36] floats  (fhalf*8+dq slices)
#define VAL_OFF   153920                 // [16] floats
#define SMEM_TOTAL 153984

typedef unsigned long long u64;

__device__ __forceinline__ u64 pack2(float a, float b) {
    u64 r;
    asm("mov.b64 %0, {%1, %2};" : "=l"(r)
        : "r"(__float_as_uint(a)), "r"(__float_as_uint(b)));
    return r;
}

__device__ __forceinline__ u64 fma2(u64 a, u64 b, u64 c) {
    u64 d;
    asm("fma.rn.f32x2 %0, %1, %2, %3;" : "=l"(d) : "l"(a), "l"(b), "l"(c));
    return d;
}

__device__ __forceinline__ void cp16(uint32_t dst, const float* src) {
    asm volatile("cp.async.cg.shared.global [%0], [%1], 16;\n"
                 :: "r"(dst), "l"(src));
}

__device__ __forceinline__ void issue_chunk(int g, int tid, uint32_t smem_base,
                                            const float* __restrict__ cores) {
    if (g < NCHUNK) {
        // gmem float idx = site*131072 + d*2048 + c*256 + w*4   (site=g>>3, c=g&7)
        const float* base = cores + (size_t)(g >> 3) * SITE_FLOATS + (g & 7) * 256;
        uint32_t dst = smem_base + (uint32_t)((g % 3) * CHUNK_BYTES) + tid * 16;
        #pragma unroll
        for (int k = 0; k < 4; ++k) {
            int u = tid + k * THREADS;        // 16B unit id, 2048 per chunk
            int d = u >> 6, w = u & 63;
            cp16(dst + k * 8192, base + d * 2048 + w * 4);
        }
    }
    asm volatile("cp.async.commit_group;\n");   // always commit (uniform counting)
}

__global__ __launch_bounds__(THREADS, 1)
void mps_encoder_kernel(const float* __restrict__ x,
                        const float* __restrict__ cores,
                        const float* __restrict__ start,
                        const float* __restrict__ endv,
                        const float* __restrict__ fc_w,
                        const float* __restrict__ fc_b,
                        float* __restrict__ out)
{
    extern __shared__ char smem[];
    float* buff  = (float*)(smem + BUF_OFF);
    u64*   x2    = (u64*)  (smem + X_OFF);     // [2][16][65]
    float* res_s = (float*)(smem + RES_OFF);   // [16][33]
    float* part  = (float*)(smem + PART_OFF);  // [16][16][36]
    float* val_s = (float*)(smem + VAL_OFF);

    const uint32_t smem_base = (uint32_t)__cvta_generic_to_shared(smem);

    const int tid   = threadIdx.x;
    const int fhalf = tid >> 8;          // 0: f-slices 0..3 of chunk, 1: 4..7
    const int bpl   = tid & 3;
    const int rq    = (tid >> 2) & 7;
    const int dq    = (tid >> 5) & 7;
    const int r0    = 4 * rq;
    const int d0    = 4 * dq;
    const int B0    = 4 * bpl;
    const int slice = fhalf * 8 + dq;    // partial-reduction slice id (0..15)
    const int bbase = blockIdx.x * NB;

    // init res = start (512 slots, 1 per thread)
    {
        int b = tid >> 5, d = tid & 31;
        res_s[b * 33 + d] = start[d];
    }

    const float4* x4 = reinterpret_cast<const float4*>(x);

    // stage x for site 0 into x-buffer 0 (duplicated pairs); threads 0..255
    if (tid < NB * 16) {
        int br = tid >> 4, q = tid & 15;
        float4 xv = x4[((size_t)(bbase + br) * NSITES + 0) * 16 + q];
        u64* dstx = &x2[(size_t)br * 65 + 4 * q];
        dstx[0] = pack2(xv.x, xv.x); dstx[1] = pack2(xv.y, xv.y);
        dstx[2] = pack2(xv.z, xv.z); dstx[3] = pack2(xv.w, xv.w);
    }

    // prologue: prefetch chunks 0 and 1
    issue_chunk(0, tid, smem_base, cores);
    issue_chunk(1, tid, smem_base, cores);

    u64 rp[4][4];     // rp[bb][i] = (res[B0+bb][d0+i], dup)
    const u64 zero = 0;

    for (int site = 0; site < NSITES; ++site) {
        u64 acc[4][2];
        #pragma unroll
        for (int bb = 0; bb < 4; ++bb) { acc[bb][0] = 0; acc[bb][1] = 0; }

        const u64* xrow = x2 + (size_t)((site & 1) * NB) * 65;

        for (int c = 0; c < CH; ++c) {
            const int g = site * CH + c;

            asm volatile("cp.async.wait_group 1;\n" ::: "memory");
            __syncthreads();                 // chunk g visible; buffer (g+2)%3 free
            issue_chunk(g + 2, tid, smem_base, cores);

            if (c == 0) {
                // stage x for next site (other x-buffer)
                if (site + 1 < NSITES && tid < NB * 16) {
                    int br = tid >> 4, q = tid & 15;
                    float4 xv = x4[((size_t)(bbase + br) * NSITES + site + 1) * 16 + q];
                    u64* dstx = &x2[(size_t)(((site + 1) & 1) * NB + br) * 65 + 4 * q];
                    dstx[0] = pack2(xv.x, xv.x); dstx[1] = pack2(xv.y, xv.y);
                    dstx[2] = pack2(xv.z, xv.z); dstx[3] = pack2(xv.w, xv.w);
                }
                // pack res pairs for this site (res_s writes ordered by sync above)
                #pragma unroll
                for (int bb = 0; bb < 4; ++bb)
                    #pragma unroll
                    for (int i = 0; i < 4; ++i) {
                        float v = res_s[(B0 + bb) * 33 + d0 + i];
                        rp[bb][i] = pack2(v, v);
                    }
            }

            // compute this half's 4 f-slices of the staged chunk
            const float* cb = buff + (size_t)(g % 3) * (CHUNK_BYTES / 4)
                            + d0 * 256 + r0 + fhalf * (4 * 32);
            #pragma unroll
            for (int fl = 0; fl < 4; ++fl) {
                ulonglong2 c0 = *(const ulonglong2*)(cb       + fl * 32);
                ulonglong2 c1 = *(const ulonglong2*)(cb + 256 + fl * 32);
                ulonglong2 c2 = *(const ulonglong2*)(cb + 512 + fl * 32);
                ulonglong2 c3 = *(const ulonglong2*)(cb + 768 + fl * 32);
                const int fg = c * CH + fhalf * 4 + fl;
                #pragma unroll
                for (int bb = 0; bb < 4; ++bb) {
                    u64 s0 = fma2(rp[bb][0], c0.x, zero);
                    u64 s1 = fma2(rp[bb][0], c0.y, zero);
                    s0 = fma2(rp[bb][1], c1.x, s0);
                    s1 = fma2(rp[bb][1], c1.y, s1);
                    s0 = fma2(rp[bb][2], c2.x, s0);
                    s1 = fma2(rp[bb][2], c2.y, s1);
                    s0 = fma2(rp[bb][3], c3.x, s0);
                    s1 = fma2(rp[bb][3], c3.y, s1);
                    u64 xv = xrow[(size_t)(B0 + bb) * 65 + fg];   // (x,x) pair
                    acc[bb][0] = fma2(xv, s0, acc[bb][0]);
                    acc[bb][1] = fma2(xv, s1, acc[bb][1]);
                }
            }
        }

        // write (fhalf, dq) partials
        #pragma unroll
        for (int bb = 0; bb < 4; ++bb) {
            float* pb = part + (size_t)(slice * NB + B0 + bb) * 36;
            *(u64*)(pb + r0)     = acc[bb][0];
            *(u64*)(pb + r0 + 2) = acc[bb][1];
        }
        __syncthreads();                    // partials visible

        // reduce 16 slices -> new res (512 slots, 1 per thread)
        {
            int b = tid >> 5, r = tid & 31;
            float v = 0.0f;
            #pragma unroll
            for (int k = 0; k < 16; ++k) v += part[(size_t)(k * NB + b) * 36 + r];
            res_s[b * 33 + r] = v;
        }
        // next site's first chunk-sync orders res_s writes before rp packing
    }

    __syncthreads();

    // val[b] = res[b] . end
    if (tid < NB) {
        float v = 0.0f;
        #pragma unroll
        for (int r = 0; r < DB; ++r) v += res_s[tid * 33 + r] * endv[r];
        val_s[tid] = v;
    }
    __syncthreads();

    // out[b][o] = val[b] * fc_w[o] + fc_b[o]   (512 threads, 8 batches each)
    {
        const int o  = tid & 255;
        const int jh = tid >> 8;
        const float w  = fc_w[o];
        const float bi = fc_b[o];
        #pragma unroll
        for (int j = 0; j < 8; ++j) {
            int b = jh * 8 + j;
            out[(size_t)(bbase + b) * OUTD + o] = val_s[b] * w + bi;
        }
    }
}

extern "C" void kernel_launch(void* const* d_in, const int* in_sizes, int n_in,
                              void* d_out, int out_size)
{
    (void)in_sizes; (void)n_in; (void)out_size;
    const float* x_p     = (const float*)d_in[0];
    const float* cores_p = (const float*)d_in[1];
    const float* start_p = (const float*)d_in[2];
    const float* end_p   = (const float*)d_in[3];
    const float* fcw_p   = (const float*)d_in[4];
    const float* fcb_p   = (const float*)d_in[5];
    float* out_p = (float*)d_out;

    cudaFuncSetAttribute(mps_encoder_kernel,
                         cudaFuncAttributeMaxDynamicSharedMemorySize, SMEM_TOTAL);

    mps_encoder_kernel<<<2048 / NB, THREADS, SMEM_TOTAL>>>(
        x_p, cores_p, start_p, end_p, fcw_p, fcb_p, out_p);
}

// round 9
// speedup vs baseline: 2.1718x; 1.0668x over previous
#include <cuda_runtime.h>
#include <cstdint>

// MPS memory encoder, Round 7: two independent barrier domains per CTA.
//   x:     [B=2048, N=128, F=64]      f32
//   cores: [N=128, D=32, F=64, D=32]  f32
//   out[B,256] = (chain(res0=start; res <- res @ (x_i . core_i)) @ end) @ fc_w^T + fc_b
//
// Geometry: grid=128 CTAs x 512 threads, NB=16 batches/CTA.
//   Half h = tid>>8 owns f-range [32h, 32h+32), with its OWN triple-buffered
//   cp.async stream (16KB chunks = 4 f-slices) and its OWN named barrier
//   (bar.sync 1+h, 256). Halves converge only at the per-site reduction.
//   Within a half: thread = 4 batches x 4 r x 4 d (bpl=tid&3, rq=(tid>>2)&7,
//   dq=(tid>>5)&7) -> LDS.128 with 4-way batch broadcast, conflict-free.

#define NSITES   128
#define FEAT     64
#define DB       32
#define OUTD     256
#define NB       16
#define THREADS  512
#define HALFT    256
#define CPS      8                        // chunks per site per half (4 f each)
#define NCHUNK_H (NSITES * CPS)           // 1024 per half
#define CHUNK_B  16384                    // 4 f-slices * 32 d * 32 r * 4B
#define SITE_FLOATS (DB * FEAT * DB)      // 131072

// smem byte offsets
#define BUF_OFF   0                       // [2 halves][3 bufs][16KB] = 96KB
#define X_OFF     98304                   // [2][16][65] u64 (x duplicated pairs)
#define RES_OFF   114944                  // [16][33] floats
#define PART_OFF  117056                  // [16][16][36] floats
#define VAL_OFF   153920                  // [16] floats
#define SMEM_TOTAL 153984

typedef unsigned long long u64;

__device__ __forceinline__ u64 pack2(float a, float b) {
    u64 r;
    asm("mov.b64 %0, {%1, %2};" : "=l"(r)
        : "r"(__float_as_uint(a)), "r"(__float_as_uint(b)));
    return r;
}

__device__ __forceinline__ u64 fma2(u64 a, u64 b, u64 c) {
    u64 d;
    asm("fma.rn.f32x2 %0, %1, %2, %3;" : "=l"(d) : "l"(a), "l"(b), "l"(c));
    return d;
}

__device__ __forceinline__ void cp16(uint32_t dst, const float* src) {
    asm volatile("cp.async.cg.shared.global [%0], [%1], 16;\n"
                 :: "r"(dst), "l"(src));
}

__device__ __forceinline__ void half_bar(int h) {
    asm volatile("bar.sync %0, %1;" :: "r"(1 + h), "r"(HALFT) : "memory");
}

// Stage chunk gh (per-half id) of this half's f-range into buffer gh%3.
//   chunk c of site s covers global f in [h*32 + c*4, +4).
//   gmem float idx = s*131072 + d*2048 + f*32 + r
//   buffer float idx = d*128 + fl*32 + r   (fl = f - chunk base)
__device__ __forceinline__ void issue_chunk(int gh, int h, int lid,
                                            uint32_t smem_base,
                                            const float* __restrict__ cores) {
    if (gh < NCHUNK_H) {
        int s = gh >> 3, c = gh & 7;
        const float* base = cores + (size_t)s * SITE_FLOATS + h * 1024 + c * 128;
        uint32_t dst = smem_base
                     + (uint32_t)((h * 3 + (gh % 3)) * CHUNK_B) + lid * 16;
        #pragma unroll
        for (int k = 0; k < 4; ++k) {
            int u = lid + k * HALFT;          // 16B unit id, 1024 per chunk
            int d = u >> 5, w = u & 31;
            cp16(dst + k * 4096, base + d * 2048 + w * 4);
        }
    }
    asm volatile("cp.async.commit_group;\n");   // uniform group counting
}

__global__ __launch_bounds__(THREADS, 1)
void mps_encoder_kernel(const float* __restrict__ x,
                        const float* __restrict__ cores,
                        const float* __restrict__ start,
                        const float* __restrict__ endv,
                        const float* __restrict__ fc_w,
                        const float* __restrict__ fc_b,
                        float* __restrict__ out)
{
    extern __shared__ char smem[];
    float* buff  = (float*)(smem + BUF_OFF);
    u64*   x2    = (u64*)  (smem + X_OFF);     // [2][16][65]
    float* res_s = (float*)(smem + RES_OFF);   // [16][33]
    float* part  = (float*)(smem + PART_OFF);  // [16][16][36]
    float* val_s = (float*)(smem + VAL_OFF);

    const uint32_t smem_base = (uint32_t)__cvta_generic_to_shared(smem);

    const int tid = threadIdx.x;
    const int h   = tid >> 8;            // half: f-range [32h, 32h+32)
    const int lid = tid & 255;
    const int bpl = tid & 3;
    const int rq  = (tid >> 2) & 7;
    const int dq  = (tid >> 5) & 7;
    const int r0  = 4 * rq;
    const int d0  = 4 * dq;
    const int B0  = 4 * bpl;
    const int slice = h * 8 + dq;        // reduction slice id (0..15)
    const int bbase = blockIdx.x * NB;

    // init res = start (512 slots, 1 per thread)
    {
        int b = tid >> 5, d = tid & 31;
        res_s[b * 33 + d] = start[d];
    }

    const float4* x4 = reinterpret_cast<const float4*>(x);

    // stage x for site 0 (threads 0..255, duplicated (x,x) pairs)
    if (tid < NB * 16) {
        int br = tid >> 4, q = tid & 15;
        float4 xv = x4[((size_t)(bbase + br) * NSITES + 0) * 16 + q];
        u64* dstx = &x2[(size_t)br * 65 + 4 * q];
        dstx[0] = pack2(xv.x, xv.x); dstx[1] = pack2(xv.y, xv.y);
        dstx[2] = pack2(xv.z, xv.z); dstx[3] = pack2(xv.w, xv.w);
    }

    // prologue: each half prefetches its chunks 0 and 1
    issue_chunk(0, h, lid, smem_base, cores);
    issue_chunk(1, h, lid, smem_base, cores);

    __syncthreads();   // x(site0) + res_s visible to all

    u64 rp[4][4];      // rp[bb][i] = (res[B0+bb][d0+i], dup)
    const u64 zero = 0;

    for (int site = 0; site < NSITES; ++site) {
        u64 acc[4][2];
        #pragma unroll
        for (int bb = 0; bb < 4; ++bb) { acc[bb][0] = 0; acc[bb][1] = 0; }

        const u64* xrow = x2 + (size_t)((site & 1) * NB) * 65;

        for (int c = 0; c < CPS; ++c) {
            const int gh = site * CPS + c;

            // own group for chunk gh landed, then half-wide visibility
            asm volatile("cp.async.wait_group 1;\n" ::: "memory");
            half_bar(h);                     // chunk gh visible; buf (gh+2)%3 free
            issue_chunk(gh + 2, h, lid, smem_base, cores);

            if (c == 0) {
                // half A stages x for next site (other parity buffer)
                if (site + 1 < NSITES && tid < NB * 16) {
                    int br = tid >> 4, q = tid & 15;
                    float4 xv = x4[((size_t)(bbase + br) * NSITES + site + 1) * 16 + q];
                    u64* dstx = &x2[(size_t)(((site + 1) & 1) * NB + br) * 65 + 4 * q];
                    dstx[0] = pack2(xv.x, xv.x); dstx[1] = pack2(xv.y, xv.y);
                    dstx[2] = pack2(xv.z, xv.z); dstx[3] = pack2(xv.w, xv.w);
                }
                // pack res pairs (res_s ordered by prev site's full sync)
                #pragma unroll
                for (int bb = 0; bb < 4; ++bb)
                    #pragma unroll
                    for (int i = 0; i < 4; ++i) {
                        float v = res_s[(B0 + bb) * 33 + d0 + i];
                        rp[bb][i] = pack2(v, v);
                    }
            }

            // compute this chunk's 4 f-slices
            const float* cb = buff + (size_t)(h * 3 + (gh % 3)) * (CHUNK_B / 4)
                            + d0 * 128 + r0;
            #pragma unroll
            for (int fl = 0; fl < 4; ++fl) {
                ulonglong2 c0 = *(const ulonglong2*)(cb       + fl * 32);
                ulonglong2 c1 = *(const ulonglong2*)(cb + 128 + fl * 32);
                ulonglong2 c2 = *(const ulonglong2*)(cb + 256 + fl * 32);
                ulonglong2 c3 = *(const ulonglong2*)(cb + 384 + fl * 32);
                const int fg = h * 32 + c * 4 + fl;
                #pragma unroll
                for (int bb = 0; bb < 4; ++bb) {
                    u64 s0 = fma2(rp[bb][0], c0.x, zero);
                    u64 s1 = fma2(rp[bb][0], c0.y, zero);
                    s0 = fma2(rp[bb][1], c1.x, s0);
                    s1 = fma2(rp[bb][1], c1.y, s1);
                    s0 = fma2(rp[bb][2], c2.x, s0);
                    s1 = fma2(rp[bb][2], c2.y, s1);
                    s0 = fma2(rp[bb][3], c3.x, s0);
                    s1 = fma2(rp[bb][3], c3.y, s1);
                    u64 xv = xrow[(size_t)(B0 + bb) * 65 + fg];   // (x,x) pair
                    acc[bb][0] = fma2(xv, s0, acc[bb][0]);
                    acc[bb][1] = fma2(xv, s1, acc[bb][1]);
                }
            }
        }

        // write (half, dq) partials
        #pragma unroll
        for (int bb = 0; bb < 4; ++bb) {
            float* pb = part + (size_t)(slice * NB + B0 + bb) * 36;
            *(u64*)(pb + r0)     = acc[bb][0];
            *(u64*)(pb + r0 + 2) = acc[bb][1];
        }
        __syncthreads();                    // all partials visible (full CTA)

        // reduce 16 slices -> new res (512 slots, 1 per thread)
        {
            int b = tid >> 5, r = tid & 31;
            float v = 0.0f;
            #pragma unroll
            for (int k = 0; k < 16; ++k) v += part[(size_t)(k * NB + b) * 36 + r];
            res_s[b * 33 + r] = v;
        }
        __syncthreads();                    // res_s + x(next) visible to both halves
    }

    // val[b] = res[b] . end
    if (tid < NB) {
        float v = 0.0f;
        #pragma unroll
        for (int r = 0; r < DB; ++r) v += res_s[tid * 33 + r] * endv[r];
        val_s[tid] = v;
    }
    __syncthreads();

    // out[b][o] = val[b] * fc_w[o] + fc_b[o]   (512 threads, 8 batches each)
    {
        const int o  = tid & 255;
        const int jh = tid >> 8;
        const float w  = fc_w[o];
        const float bi = fc_b[o];
        #pragma unroll
        for (int j = 0; j < 8; ++j) {
            int b = jh * 8 + j;
            out[(size_t)(bbase + b) * OUTD + o] = val_s[b] * w + bi;
        }
    }
}

extern "C" void kernel_launch(void* const* d_in, const int* in_sizes, int n_in,
                              void* d_out, int out_size)
{
    (void)in_sizes; (void)n_in; (void)out_size;
    const float* x_p     = (const float*)d_in[0];
    const float* cores_p = (const float*)d_in[1];
    const float* start_p = (const float*)d_in[2];
    const float* end_p   = (const float*)d_in[3];
    const float* fcw_p   = (const float*)d_in[4];
    const float* fcb_p   = (const float*)d_in[5];
    float* out_p = (float*)d_out;

    cudaFuncSetAttribute(mps_encoder_kernel,
                         cudaFuncAttributeMaxDynamicSharedMemorySize, SMEM_TOTAL);

    mps_encoder_kernel<<<2048 / NB, THREADS, SMEM_TOTAL>>>(
        x_p, cores_p, start_p, end_p, fcw_p, fcb_p, out_p);
}